// round 6
// baseline (speedup 1.0000x reference)
#include <cuda_runtime.h>

// ADSR envelope, closed form per row (gate = prefix of 1s of length th):
//   t <  th, t+1 <= attack : (t+1)/attack
//   t <  th, t+1 >  attack : s + (1-s) * dtc^(t+1-attack)
//   t >= th                : D * rtc^(t-th+1),  D = s + (1-s)*dtc^(th-attack+1)
// dtc/rtc are the f32-rounded exp(-1/decay), exp(-1/release) — these must
// match the reference's rounding (error amplified ~exponent x by the power);
// one-shot exponentials use ex2.approx (error ~2^-22, unamplified).
//
// R5 lesson: search embedded in every eval block = 16x redundant 256-line
// gathers + 2 barriers on every block's critical path; ncu kernel time was
// flat ~11-13us across 5 kernel shapes (latency-bound, all pipes <40%).
// Split: prep kernel does the search once per row (64 blocks) into __device__
// tables; eval is barrier-free, gather-free, pure coalesced stores.

#define T_LEN   131072          // 2^17, fixed
#define T_SHIFT 17
#define EPB     8192            // eval: 256 threads * 32 elements; 16 blocks/row
#define MAX_B   256

__device__ float4 g_par[3];     // {attack,1/attack,s,1-s} {l2dtc,l2rtc,dtc,rtc} {r128,d128,-,-}
__device__ float2 g_rowDT[MAX_B]; // {D, th as int bits}

__device__ __forceinline__ float ex2(float x) {
    float r;
    asm("ex2.approx.f32 %0, %1;" : "=f"(r) : "f"(x));
    return r;
}

// ---------------- prep: one block per row, 2-round search ----------------
__global__ void __launch_bounds__(256)
adsr_prep(const float* __restrict__ gate,
          const float* __restrict__ p_attack,
          const float* __restrict__ p_decay,
          const float* __restrict__ p_sustain,
          const float* __restrict__ p_release)
{
    const int tid  = threadIdx.x;
    const int wid  = tid >> 5;
    const int lane = tid & 31;
    const float* row = gate + (size_t)blockIdx.x * T_LEN;

    // round-1 probe first: DRAM latency covers nothing else here, but issue it early
    float probe1 = __ldg(&row[tid * 512 + 511]);

    __shared__ int sh1[8], sh2[8];

    int w1 = __reduce_add_sync(0xffffffffu, probe1 != 0.0f ? 1 : 0);
    if (lane == 0) sh1[wid] = w1;
    __syncthreads();
    int lo = 0;
#pragma unroll
    for (int i = 0; i < 8; ++i) lo += sh1[i];
    lo *= 512;
    lo = min(lo, T_LEN - 512);

    float2 g2 = *reinterpret_cast<const float2*>(row + lo + 2 * tid);
    int w2 = __reduce_add_sync(0xffffffffu, (g2.x != 0.0f) + (g2.y != 0.0f));
    if (lane == 0) sh2[wid] = w2;
    __syncthreads();

    if (tid == 0) {
        int th = lo;
#pragma unroll
        for (int i = 0; i < 8; ++i) th += sh2[i];

        float attack  = *p_attack;
        float decay   = *p_decay;
        float s       = *p_sustain;
        float release = *p_release;
        float dtc = expf(-1.0f / decay);    // precise: must match reference
        float rtc = expf(-1.0f / release);
        float log_dtc = logf(dtc);
        const float L2E = 1.4426950408889634f;
        float l2dtc = log_dtc * L2E;
        float l2rtc = logf(rtc) * L2E;

        float D = s + (1.0f - s) * expf(((float)th - attack + 1.0f) * log_dtc);
        g_rowDT[blockIdx.x] = make_float2(D, __int_as_float(th));

        if (blockIdx.x == 0) {
            g_par[0] = make_float4(attack, 1.0f / attack, s, 1.0f - s);
            g_par[1] = make_float4(l2dtc, l2rtc, dtc, rtc);
            g_par[2] = make_float4(ex2(128.0f * l2rtc), ex2(128.0f * l2dtc), 0.f, 0.f);
        }
    }
}

// ---------------- eval: barrier-free, gather-free, pure stores ----------------
__global__ void __launch_bounds__(256, 8)
adsr_eval(float* __restrict__ out)
{
    const int tid  = threadIdx.x;
    const int wid  = tid >> 5;
    const int lane = tid & 31;

    const int blk_base = blockIdx.x * EPB;          // ~8.4M elems: fits int
    const int b   = blk_base >> T_SHIFT;
    const int seg = blk_base & (T_LEN - 1);

    // single dependent load chain: per-row info + params (L2-broadcast)
    const float2 ri = g_rowDT[b];
    const float4 p0 = g_par[0];
    const float4 p1 = g_par[1];
    const float4 p2 = g_par[2];

    const float D  = ri.x;
    const int   th = __float_as_int(ri.y);
    const float attack = p0.x, ia    = p0.y, s   = p0.z, oms = p0.w;
    const float l2dtc  = p1.x, l2rtc = p1.y, dtc = p1.z, rtc = p1.w;
    const float r128   = p2.x, d128  = p2.y;

    // warp owns 1024 contiguous elems; thread owns 8 runs of 4 spaced 128
    // apart -> each STG.128 is a fully coalesced 512B warp store
    const int wbase = seg + wid * 1024;
    const int t0    = wbase + lane * 4;
    float4* owp = reinterpret_cast<float4*>(out + blk_base + wid * 1024);

    if (wbase >= th) {
        // pure release span
        float w = D * ex2((float)(t0 - th + 1) * l2rtc);
#pragma unroll
        for (int j = 0; j < 8; ++j) {
            float a = w, c = a * rtc, d = c * rtc, e = d * rtc;
            owp[j * 32 + lane] = make_float4(a, c, d, e);
            w *= r128;
        }
    } else if (wbase + 1024 <= th && (float)(wbase + 1) > attack) {
        // pure decay span
        float w = oms * ex2(((float)(t0 + 1) - attack) * l2dtc);
#pragma unroll
        for (int j = 0; j < 8; ++j) {
            float a = w, c = a * dtc, d = c * dtc, e = d * dtc;
            owp[j * 32 + lane] = make_float4(s + a, s + c, s + d, s + e);
            w *= d128;
        }
    } else {
        // mixed span (rare): run-level dispatch; per-element only for the
        // (at most 2) boundary runs
#pragma unroll 1
        for (int j = 0; j < 8; ++j) {
            int rb = wbase + j * 128;         // run base, lane-uniform
            int t  = rb + lane * 4;
            float4 v;
            if (rb >= th) {
                float a = D * ex2((float)(t - th + 1) * l2rtc);
                float c = a * rtc, d = c * rtc, e = d * rtc;
                v = make_float4(a, c, d, e);
            } else if (rb + 128 <= th && (float)(rb + 128) <= attack) {
                float base = (float)(t + 1) * ia;
                v = make_float4(base, base + ia, base + 2.0f * ia, base + 3.0f * ia);
            } else if (rb + 128 <= th && (float)(rb + 1) > attack) {
                float a = oms * ex2(((float)(t + 1) - attack) * l2dtc);
                float c = a * dtc, d = c * dtc, e = d * dtc;
                v = make_float4(s + a, s + c, s + d, s + e);
            } else {
                float* vp = &v.x;
#pragma unroll
                for (int k = 0; k < 4; ++k) {
                    int tt = t + k;
                    float r;
                    if (tt >= th) {
                        r = D * ex2((float)(tt - th + 1) * l2rtc);
                    } else {
                        float x = (float)(tt + 1);
                        r = (x <= attack) ? x * ia
                                          : s + oms * ex2((x - attack) * l2dtc);
                    }
                    vp[k] = r;
                }
            }
            owp[j * 32 + lane] = v;
        }
    }
}

extern "C" void kernel_launch(void* const* d_in, const int* in_sizes, int n_in,
                              void* d_out, int out_size)
{
    const float* gate      = (const float*)d_in[0];
    const float* p_attack  = (const float*)d_in[1];
    const float* p_decay   = (const float*)d_in[2];
    const float* p_sustain = (const float*)d_in[3];
    const float* p_release = (const float*)d_in[4];
    float* out = (float*)d_out;

    int B = in_sizes[0] / T_LEN;
    if (B > MAX_B) B = MAX_B;

    adsr_prep<<<B, 256>>>(gate, p_attack, p_decay, p_sustain, p_release);

    int blocks = out_size / EPB;
    adsr_eval<<<blocks, 256>>>(out);
}